// round 5
// baseline (speedup 1.0000x reference)
#include <cuda_runtime.h>
#include <math.h>
#include <stdint.h>

// Problem constants
#define T_TOK 2048
#define DDIM  2048
#define NEXP  16
#define IDIM  1024
#define SIDIM 2048
#define KTOP  4

// ---------------- scratch (__device__ globals, allocation-free) ----------------
__device__ float g_h_shared[(size_t)T_TOK * SIDIM];
__device__ float g_h_moe[(size_t)T_TOK * KTOP * IDIM];
__device__ float g_y_moe[(size_t)T_TOK * KTOP * DDIM];
__device__ int   g_counts[NEXP];
__device__ int   g_rows[NEXP * T_TOK];
__device__ float g_slotw[T_TOK * KTOP];
// tf32-preconverted operands
__device__ float g_x_t[(size_t)T_TOK * DDIM];
__device__ float g_wgu_t[(size_t)NEXP * DDIM * 2 * IDIM];
__device__ float g_wd_t[(size_t)NEXP * IDIM * DDIM];
__device__ float g_wsgu_t[(size_t)DDIM * 2 * SIDIM];
__device__ float g_wsd_t[(size_t)SIDIM * DDIM];

// ---------------- helpers ----------------
__device__ __forceinline__ uint32_t f2tf(float f) {
    uint32_t r;
    asm("cvt.rna.tf32.f32 %0, %1;" : "=r"(r) : "f"(f));
    return r;
}
__device__ __forceinline__ uint4 cvt4(float4 v) {
    uint4 t;
    t.x = f2tf(v.x); t.y = f2tf(v.y); t.z = f2tf(v.z); t.w = f2tf(v.w);
    return t;
}
__device__ __forceinline__ void mma8(float c[4], const uint32_t a[4], const uint32_t b[2]) {
    asm volatile(
        "mma.sync.aligned.m16n8k8.row.col.f32.tf32.tf32.f32 "
        "{%0,%1,%2,%3}, {%4,%5,%6,%7}, {%8,%9}, {%0,%1,%2,%3};"
        : "+f"(c[0]), "+f"(c[1]), "+f"(c[2]), "+f"(c[3])
        : "r"(a[0]), "r"(a[1]), "r"(a[2]), "r"(a[3]), "r"(b[0]), "r"(b[1]));
}
__device__ __forceinline__ void ldsm4(uint32_t (&r)[4], uint32_t addr) {
    asm volatile("ldmatrix.sync.aligned.m8n8.x4.shared.b16 {%0,%1,%2,%3}, [%4];"
                 : "=r"(r[0]), "=r"(r[1]), "=r"(r[2]), "=r"(r[3]) : "r"(addr));
}
__device__ __forceinline__ uint32_t smem_u32(const void* p) {
    uint32_t a;
    asm("{ .reg .u64 t; cvta.to.shared.u64 t, %1; cvt.u32.u64 %0, t; }" : "=r"(a) : "l"(p));
    return a;
}
__device__ __forceinline__ void cp16(uint32_t saddr, const void* gptr, uint32_t sz) {
    asm volatile("cp.async.cg.shared.global [%0], [%1], 16, %2;"
                 :: "r"(saddr), "l"(gptr), "r"(sz) : "memory");
}
#define CP_COMMIT() asm volatile("cp.async.commit_group;" ::: "memory")
#define CP_WAIT2()  asm volatile("cp.async.wait_group 2;" ::: "memory")

// smem stage: A 4096 words + B 4352 words (32 rows x 136 incl pad) = 8448 words
#define STG_WORDS 8448
#define STG_BYTES (STG_WORDS * 4)          // 33792
#define SM_BYTES  (3 * STG_BYTES)          // 101376

// ---------------- conversion kernel: dst = tf32_rna(src), 4-way MLP ----------------
__global__ void cvt_kernel(const float4* __restrict__ src, float4* __restrict__ dst, int n4) {
    const int stride = gridDim.x * blockDim.x;
    int i = blockIdx.x * blockDim.x + threadIdx.x;
    for (; i + 3 * stride < n4; i += 4 * stride) {
        float4 v0 = src[i];
        float4 v1 = src[i + stride];
        float4 v2 = src[i + 2 * stride];
        float4 v3 = src[i + 3 * stride];
        uint4 t0 = cvt4(v0), t1 = cvt4(v1), t2 = cvt4(v2), t3 = cvt4(v3);
        dst[i]              = *(float4*)&t0;
        dst[i + stride]     = *(float4*)&t1;
        dst[i + 2 * stride] = *(float4*)&t2;
        dst[i + 3 * stride] = *(float4*)&t3;
    }
    for (; i < n4; i += stride) {
        uint4 t = cvt4(src[i]);
        dst[i] = *(float4*)&t;
    }
}

// ---------------- init + router ----------------
__global__ void init_kernel() {
    if (threadIdx.x < NEXP) g_counts[threadIdx.x] = 0;
}

__global__ void router_kernel(const float* __restrict__ x,
                              const float* __restrict__ gw,
                              const float* __restrict__ gb) {
    int wid  = threadIdx.x >> 5;
    int lane = threadIdx.x & 31;
    int t = blockIdx.x * (blockDim.x >> 5) + wid;
    if (t >= T_TOK) return;

    float acc[NEXP];
#pragma unroll
    for (int e = 0; e < NEXP; e++) acc[e] = 0.f;
    const float* xr = x + (size_t)t * DDIM;
    for (int j = lane; j < DDIM; j += 32) {
        float xv = xr[j];
#pragma unroll
        for (int e = 0; e < NEXP; e++) acc[e] += xv * gw[e * DDIM + j];
    }
#pragma unroll
    for (int e = 0; e < NEXP; e++) {
#pragma unroll
        for (int off = 16; off > 0; off >>= 1)
            acc[e] += __shfl_xor_sync(0xffffffffu, acc[e], off);
    }
    float mx = acc[0];
#pragma unroll
    for (int e = 1; e < NEXP; e++) mx = fmaxf(mx, acc[e]);
    float p[NEXP]; float sum = 0.f;
#pragma unroll
    for (int e = 0; e < NEXP; e++) { p[e] = expf(acc[e] - mx); sum += p[e]; }
    float inv = 1.f / sum;
#pragma unroll
    for (int e = 0; e < NEXP; e++) p[e] *= inv;
    float bmin = gb[0];
#pragma unroll
    for (int e = 1; e < NEXP; e++) bmin = fminf(bmin, gb[e]);
    float sel[NEXP];
#pragma unroll
    for (int e = 0; e < NEXP; e++) sel[e] = p[e] + (gb[e] - bmin);
    int idx[KTOP]; float w[KTOP]; float wsum = 0.f;
#pragma unroll
    for (int s = 0; s < KTOP; s++) {
        int best = 0; float bv = sel[0];
#pragma unroll
        for (int e = 1; e < NEXP; e++) { if (sel[e] > bv) { bv = sel[e]; best = e; } }
        idx[s] = best; w[s] = p[best]; wsum += p[best];
        sel[best] = -1e30f;
    }
    float invw = 1.f / wsum;
    if (lane == 0) {
#pragma unroll
        for (int s = 0; s < KTOP; s++) {
            int slot = t * KTOP + s;
            g_slotw[slot] = w[s] * invw;
            int pos = atomicAdd(&g_counts[idx[s]], 1);
            g_rows[idx[s] * T_TOK + pos] = slot;
        }
    }
}

// ---------------- tf32 mma.sync GEMM (cp.async 3-stage, 2 CTA/SM, ldmatrix A) ---------
template <bool GATHER, bool SWIGLU, bool SCALE, int SHIFT, bool CVTOUT>
__global__ void __launch_bounds__(256, 2)
tgemm(const float* __restrict__ A, const float* __restrict__ Bmat,
      float* __restrict__ C, int K, int lda, int ldb, int ldc,
      long long bstride, int uoff)
{
    int n = 0x7fffffff;
    const int* rowlist = nullptr;
    const float* B = Bmat;
    if (GATHER) {
        int e = blockIdx.z;
        n = g_counts[e];
        if ((int)(blockIdx.y * 128) >= n) return;
        rowlist = g_rows + e * T_TOK;
        B = Bmat + (long long)e * bstride;
    }

    extern __shared__ uint32_t smem[];
    const uint32_t sbase = smem_u32(smem);
    const int tid = threadIdx.x;
    const int wid = tid >> 5, lane = tid & 31;
    const int gid = lane >> 2, tig = lane & 3;
    const int wm = wid & 3, wn = wid >> 2;
    const int row0 = blockIdx.y * 128;
    const int BNout = SWIGLU ? 64 : 128;
    const int c0 = blockIdx.x * BNout;

    // staging descriptors
    int aoff[4]; uint32_t asz[4]; uint32_t asw[4];
#pragma unroll
    for (int i = 0; i < 4; i++) {
        int f4 = tid + i * 256;
        int m = f4 >> 3, k4 = f4 & 7;
        asw[i] = (uint32_t)(m * 32 + ((k4 ^ (m & 7)) << 2)) * 4;
        int r = row0 + m;
        if (GATHER) {
            if (r < n) { aoff[i] = (rowlist[r] >> SHIFT) * lda + k4 * 4; asz[i] = 16; }
            else       { aoff[i] = 0; asz[i] = 0; }
        } else { aoff[i] = r * lda + k4 * 4; asz[i] = 16; }
    }
    int boff[4]; uint32_t bsw[4];
#pragma unroll
    for (int i = 0; i < 4; i++) {
        int f4 = tid + i * 256;
        int k = f4 >> 5, n4 = f4 & 31;
        int gcol;
        if (SWIGLU) {
            int t  = n4 >> 2;
            int up = (n4 >> 1) & 1;
            int ci = (n4 & 1) * 4;
            gcol = (up ? uoff : 0) + c0 + t * 8 + ci;
        } else {
            gcol = c0 + n4 * 4;
        }
        boff[i] = k * ldb + gcol;
        bsw[i] = (uint32_t)(4096 + k * 136 + n4 * 4) * 4;
    }

    // ldmatrix per-lane A addressing: row = wm*32 + mt*16 + (lane&15),
    // col-block = ks*2 + (lane>>4), byte = row*128 + ((cb ^ (row&7))<<4)
    const uint32_t lan7 = (uint32_t)(lane & 7);
    const uint32_t lhi  = (uint32_t)(lane >> 4);
    const uint32_t arow = (uint32_t)(wm * 32 + (lane & 15)) * 128;

    float acc[2][8][4];
#pragma unroll
    for (int mt = 0; mt < 2; mt++)
#pragma unroll
        for (int j = 0; j < 8; j++)
#pragma unroll
            for (int q = 0; q < 4; q++) acc[mt][j][q] = 0.f;

    const int NC = K / 32;

#define ISSUE(ch)                                                            \
    {                                                                        \
        const uint32_t sb_ = sbase + (uint32_t)((ch) % 3) * STG_BYTES;       \
        const int ka_ = (ch) * 32;                                           \
        const int kb_ = (ch) * 32 * ldb;                                     \
        _Pragma("unroll")                                                    \
        for (int i = 0; i < 4; i++) cp16(sb_ + asw[i], A + aoff[i] + ka_, asz[i]); \
        _Pragma("unroll")                                                    \
        for (int i = 0; i < 4; i++) cp16(sb_ + bsw[i], B + boff[i] + kb_, 16u); \
    }

    ISSUE(0); CP_COMMIT();
    ISSUE(1); CP_COMMIT();

    for (int ch = 0; ch < NC; ch++) {
        if (ch + 2 < NC) { ISSUE(ch + 2); }
        CP_COMMIT();
        CP_WAIT2();
        __syncthreads();

        const uint32_t aSt = sbase + (uint32_t)(ch % 3) * STG_BYTES;
        const uint32_t* Bs = smem + (ch % 3) * STG_WORDS + 4096;
#pragma unroll
        for (int ks = 0; ks < 4; ks++) {
            uint32_t a[2][4];
            const uint32_t xo = ((uint32_t)(ks * 2) + lhi) ^ lan7;
            ldsm4(a[0], aSt + arow + (xo << 4));
            ldsm4(a[1], aSt + arow + 2048 + (xo << 4));
            uint32_t b[8][2];
            const uint32_t* bp = Bs + (ks * 8 + tig) * 136 + wn * 64 + gid;
#pragma unroll
            for (int j = 0; j < 8; j++) {
                b[j][0] = bp[j * 8];
                b[j][1] = bp[544 + j * 8];
            }
#pragma unroll
            for (int mt = 0; mt < 2; mt++)
#pragma unroll
                for (int j = 0; j < 8; j++)
                    mma8(acc[mt][j], a[mt], b[j]);
        }
        __syncthreads();
    }
#undef ISSUE

    // ---- epilogue ----
#pragma unroll
    for (int mt = 0; mt < 2; mt++) {
#pragma unroll
        for (int h = 0; h < 2; h++) {
            int r = row0 + wm * 32 + mt * 16 + gid + h * 8;
            bool valid = GATHER ? (r < n) : true;
            if (!valid) continue;
            int crow; float scale = 1.f;
            if (GATHER) {
                int slot = rowlist[r];
                crow = slot;
                if (SCALE) scale = g_slotw[slot];
            } else crow = r;
            float* cp = C + (long long)crow * ldc;
            if (SWIGLU) {
#pragma unroll
                for (int t2 = 0; t2 < 4; t2++) {
                    float g0 = acc[mt][t2 * 2][h * 2 + 0];
                    float g1 = acc[mt][t2 * 2][h * 2 + 1];
                    float u0 = acc[mt][t2 * 2 + 1][h * 2 + 0];
                    float u1 = acc[mt][t2 * 2 + 1][h * 2 + 1];
                    float2 o;
                    o.x = g0 / (1.f + expf(-g0)) * u0;
                    o.y = g1 / (1.f + expf(-g1)) * u1;
                    if (CVTOUT) {
                        o.x = __uint_as_float(f2tf(o.x));
                        o.y = __uint_as_float(f2tf(o.y));
                    }
                    *(float2*)(cp + c0 + (wn * 4 + t2) * 8 + tig * 2) = o;
                }
            } else {
#pragma unroll
                for (int j = 0; j < 8; j++) {
                    float2 o;
                    o.x = acc[mt][j][h * 2 + 0] * scale;
                    o.y = acc[mt][j][h * 2 + 1] * scale;
                    if (CVTOUT) {
                        o.x = __uint_as_float(f2tf(o.x));
                        o.y = __uint_as_float(f2tf(o.y));
                    }
                    *(float2*)(cp + c0 + (wn * 8 + j) * 8 + tig * 2) = o;
                }
            }
        }
    }
}

// ---------------- combine ----------------
__global__ void combine_kernel(float* __restrict__ out) {
    long long i = (long long)blockIdx.x * blockDim.x + threadIdx.x;
    const long long nf4 = (long long)T_TOK * DDIM / 4;
    if (i >= nf4) return;
    long long t = i / (DDIM / 4);
    int c = (int)(i % (DDIM / 4)) * 4;
    float4 o = *(float4*)(out + t * DDIM + c);
#pragma unroll
    for (int s = 0; s < KTOP; s++) {
        const float4 y = *(const float4*)(g_y_moe + ((t * KTOP + s) * (long long)DDIM) + c);
        o.x += y.x; o.y += y.y; o.z += y.z; o.w += y.w;
    }
    *(float4*)(out + t * DDIM + c) = o;
}

// ---------------- host ----------------
static float* sym_f(const void* symbol) {
    void* p = nullptr;
    cudaGetSymbolAddress(&p, symbol);
    return (float*)p;
}

extern "C" void kernel_launch(void* const* d_in, const int* in_sizes, int n_in,
                              void* d_out, int out_size) {
    (void)in_sizes; (void)n_in; (void)out_size;
    const float* x    = (const float*)d_in[0];
    const float* gw   = (const float*)d_in[1];
    const float* gb   = (const float*)d_in[2];
    const float* wgu  = (const float*)d_in[3];
    const float* wd   = (const float*)d_in[4];
    const float* wsgu = (const float*)d_in[5];
    const float* wsd  = (const float*)d_in[6];
    float* out = (float*)d_out;

    float* h_shared = sym_f(g_h_shared);
    float* h_moe    = sym_f(g_h_moe);
    float* y_moe    = sym_f(g_y_moe);
    float* x_t      = sym_f(g_x_t);
    float* wgu_t    = sym_f(g_wgu_t);
    float* wd_t     = sym_f(g_wd_t);
    float* wsgu_t   = sym_f(g_wsgu_t);
    float* wsd_t    = sym_f(g_wsd_t);

    cudaFuncSetAttribute(tgemm<false, true,  false, 0, true >, cudaFuncAttributeMaxDynamicSharedMemorySize, SM_BYTES);
    cudaFuncSetAttribute(tgemm<false, false, false, 0, false>, cudaFuncAttributeMaxDynamicSharedMemorySize, SM_BYTES);
    cudaFuncSetAttribute(tgemm<true,  true,  false, 2, true >, cudaFuncAttributeMaxDynamicSharedMemorySize, SM_BYTES);
    cudaFuncSetAttribute(tgemm<true,  false, true,  0, false>, cudaFuncAttributeMaxDynamicSharedMemorySize, SM_BYTES);

    // tf32 pre-conversion passes
    cvt_kernel<<<2048, 256>>>((const float4*)x,    (float4*)x_t,    (int)((size_t)T_TOK * DDIM / 4));
    cvt_kernel<<<4096, 256>>>((const float4*)wgu,  (float4*)wgu_t,  (int)((size_t)NEXP * DDIM * 2 * IDIM / 4));
    cvt_kernel<<<4096, 256>>>((const float4*)wd,   (float4*)wd_t,   (int)((size_t)NEXP * IDIM * DDIM / 4));
    cvt_kernel<<<2048, 256>>>((const float4*)wsgu, (float4*)wsgu_t, (int)((size_t)DDIM * 2 * SIDIM / 4));
    cvt_kernel<<<2048, 256>>>((const float4*)wsd,  (float4*)wsd_t,  (int)((size_t)SIDIM * DDIM / 4));

    init_kernel<<<1, 32>>>();
    router_kernel<<<T_TOK / 8, 256>>>(x, gw, gb);

    // shared gate_up + SwiGLU: x_t[T,D] @ wsgu_t[D,2SI] -> h_shared[T,SI] (tf32-rounded)
    tgemm<false, true, false, 0, true>
        <<<dim3(SIDIM / 64, T_TOK / 128, 1), 256, SM_BYTES>>>(
            x_t, wsgu_t, h_shared, DDIM, DDIM, 2 * SIDIM, SIDIM, 0, SIDIM);

    // shared down: h_shared @ wsd_t -> out (dense write covers poison)
    tgemm<false, false, false, 0, false>
        <<<dim3(DDIM / 128, T_TOK / 128, 1), 256, SM_BYTES>>>(
            h_shared, wsd_t, out, SIDIM, SIDIM, DDIM, DDIM, 0, 0);

    // routed gate_up + SwiGLU (gather tokens): x_t @ wgu_t[e] -> h_moe[slot, I] (tf32-rounded)
    tgemm<true, true, false, 2, true>
        <<<dim3(IDIM / 64, T_TOK / 128, NEXP), 256, SM_BYTES>>>(
            x_t, wgu_t, h_moe, DDIM, DDIM, 2 * IDIM, IDIM,
            (long long)DDIM * 2 * IDIM, IDIM);

    // routed down (gather slots, scale): h_moe @ wd_t[e] -> y_moe[slot, D]
    tgemm<true, false, true, 0, false>
        <<<dim3(DDIM / 128, T_TOK / 128, NEXP), 256, SM_BYTES>>>(
            h_moe, wd_t, y_moe, IDIM, IDIM, DDIM, DDIM,
            (long long)IDIM * DDIM, 0);

    combine_kernel<<<(T_TOK * DDIM / 4 + 255) / 256, 256>>>(out);
}

// round 8
// speedup vs baseline: 1.4690x; 1.4690x over previous
#include <cuda_runtime.h>
#include <math.h>
#include <stdint.h>

// Problem constants
#define T_TOK 2048
#define DDIM  2048
#define NEXP  16
#define IDIM  1024
#define SIDIM 2048
#define KTOP  4

// ---------------- scratch (__device__ globals, allocation-free) ----------------
__device__ float g_h_shared[(size_t)T_TOK * SIDIM];
__device__ float g_h_moe[(size_t)T_TOK * KTOP * IDIM];
__device__ float g_y_moe[(size_t)T_TOK * KTOP * DDIM];
__device__ int   g_counts[NEXP];
__device__ int   g_rows[NEXP * T_TOK];
__device__ float g_slotw[T_TOK * KTOP];
// tf32-preconverted operands
__device__ float g_x_t[(size_t)T_TOK * DDIM];
__device__ float g_wgu_t[(size_t)NEXP * DDIM * 2 * IDIM];
__device__ float g_wd_t[(size_t)NEXP * IDIM * DDIM];
__device__ float g_wsgu_t[(size_t)DDIM * 2 * SIDIM];
__device__ float g_wsd_t[(size_t)SIDIM * DDIM];

// ---------------- helpers ----------------
__device__ __forceinline__ uint32_t f2tf(float f) {
    uint32_t r;
    asm("cvt.rna.tf32.f32 %0, %1;" : "=r"(r) : "f"(f));
    return r;
}
__device__ __forceinline__ uint4 cvt4(float4 v) {
    uint4 t;
    t.x = f2tf(v.x); t.y = f2tf(v.y); t.z = f2tf(v.z); t.w = f2tf(v.w);
    return t;
}
__device__ __forceinline__ void mma8(float c[4], const uint32_t a[4], const uint32_t b[2]) {
    asm volatile(
        "mma.sync.aligned.m16n8k8.row.col.f32.tf32.tf32.f32 "
        "{%0,%1,%2,%3}, {%4,%5,%6,%7}, {%8,%9}, {%0,%1,%2,%3};"
        : "+f"(c[0]), "+f"(c[1]), "+f"(c[2]), "+f"(c[3])
        : "r"(a[0]), "r"(a[1]), "r"(a[2]), "r"(a[3]), "r"(b[0]), "r"(b[1]));
}
__device__ __forceinline__ uint32_t smem_u32(const void* p) {
    uint32_t a;
    asm("{ .reg .u64 t; cvta.to.shared.u64 t, %1; cvt.u32.u64 %0, t; }" : "=r"(a) : "l"(p));
    return a;
}
__device__ __forceinline__ void cp16(uint32_t saddr, const void* gptr, uint32_t sz) {
    asm volatile("cp.async.cg.shared.global [%0], [%1], 16, %2;"
                 :: "r"(saddr), "l"(gptr), "r"(sz) : "memory");
}
#define CP_COMMIT() asm volatile("cp.async.commit_group;" ::: "memory")
#define CP_WAIT1()  asm volatile("cp.async.wait_group 1;" ::: "memory")

// smem stage: A 4096 words + B 4352 words (32 rows x 136 incl pad) = 8448 words
#define STG_WORDS 8448
#define STG_BYTES (STG_WORDS * 4)          // 33792
#define SM_BYTES  (3 * STG_BYTES)          // 101376

// ---------------- conversion kernel: dst = tf32_rna(src) ----------------
// Each block owns super-tiles of 2048 float4s; each thread performs 8
// independent coalesced LDG.128 (lanes 16B apart, k-steps 256 float4 apart).
// All n4 passed in are multiples of 2048, so no bounds checks in the body.
__global__ void cvt_kernel(const float4* __restrict__ src, float4* __restrict__ dst, int n4) {
    const long long step = (long long)gridDim.x * 2048;
    for (long long base = (long long)blockIdx.x * 2048 + threadIdx.x; base < n4; base += step) {
        float4 v[8];
#pragma unroll
        for (int k = 0; k < 8; k++) v[k] = src[base + k * 256];
        uint4 t[8];
#pragma unroll
        for (int k = 0; k < 8; k++) t[k] = cvt4(v[k]);
#pragma unroll
        for (int k = 0; k < 8; k++) dst[base + k * 256] = *(float4*)&t[k];
    }
}

// ---------------- init + router ----------------
__global__ void init_kernel() {
    if (threadIdx.x < NEXP) g_counts[threadIdx.x] = 0;
}

__global__ void router_kernel(const float* __restrict__ x,
                              const float* __restrict__ gw,
                              const float* __restrict__ gb) {
    int wid  = threadIdx.x >> 5;
    int lane = threadIdx.x & 31;
    int t = blockIdx.x * (blockDim.x >> 5) + wid;
    if (t >= T_TOK) return;

    float acc[NEXP];
#pragma unroll
    for (int e = 0; e < NEXP; e++) acc[e] = 0.f;
    const float* xr = x + (size_t)t * DDIM;
    for (int j = lane; j < DDIM; j += 32) {
        float xv = xr[j];
#pragma unroll
        for (int e = 0; e < NEXP; e++) acc[e] += xv * gw[e * DDIM + j];
    }
#pragma unroll
    for (int e = 0; e < NEXP; e++) {
#pragma unroll
        for (int off = 16; off > 0; off >>= 1)
            acc[e] += __shfl_xor_sync(0xffffffffu, acc[e], off);
    }
    float mx = acc[0];
#pragma unroll
    for (int e = 1; e < NEXP; e++) mx = fmaxf(mx, acc[e]);
    float p[NEXP]; float sum = 0.f;
#pragma unroll
    for (int e = 0; e < NEXP; e++) { p[e] = expf(acc[e] - mx); sum += p[e]; }
    float inv = 1.f / sum;
#pragma unroll
    for (int e = 0; e < NEXP; e++) p[e] *= inv;
    float bmin = gb[0];
#pragma unroll
    for (int e = 1; e < NEXP; e++) bmin = fminf(bmin, gb[e]);
    float sel[NEXP];
#pragma unroll
    for (int e = 0; e < NEXP; e++) sel[e] = p[e] + (gb[e] - bmin);
    int idx[KTOP]; float w[KTOP]; float wsum = 0.f;
#pragma unroll
    for (int s = 0; s < KTOP; s++) {
        int best = 0; float bv = sel[0];
#pragma unroll
        for (int e = 1; e < NEXP; e++) { if (sel[e] > bv) { bv = sel[e]; best = e; } }
        idx[s] = best; w[s] = p[best]; wsum += p[best];
        sel[best] = -1e30f;
    }
    float invw = 1.f / wsum;
    if (lane == 0) {
#pragma unroll
        for (int s = 0; s < KTOP; s++) {
            int slot = t * KTOP + s;
            g_slotw[slot] = w[s] * invw;
            int pos = atomicAdd(&g_counts[idx[s]], 1);
            g_rows[idx[s] * T_TOK + pos] = slot;
        }
    }
}

// ---------------- tf32 mma.sync GEMM (cp.async 3-stage, single-barrier) ----------------
// Operands PRE-CONVERTED tf32-in-fp32. Block tile 128 x (SWIGLU?64:128) x K, BK=32,
// 8 warps (4M x 2N). Fragment loads via scalar LDS (R4-validated fast path).
template <bool GATHER, bool SWIGLU, bool SCALE, int SHIFT, bool CVTOUT>
__global__ void __launch_bounds__(256, 2)
tgemm(const float* __restrict__ A, const float* __restrict__ Bmat,
      float* __restrict__ C, int K, int lda, int ldb, int ldc,
      long long bstride, int uoff)
{
    int n = 0x7fffffff;
    const int* rowlist = nullptr;
    const float* B = Bmat;
    if (GATHER) {
        int e = blockIdx.z;
        n = g_counts[e];
        if ((int)(blockIdx.y * 128) >= n) return;
        rowlist = g_rows + e * T_TOK;
        B = Bmat + (long long)e * bstride;
    }

    extern __shared__ uint32_t smem[];
    const uint32_t sbase = smem_u32(smem);
    const int tid = threadIdx.x;
    const int wid = tid >> 5, lane = tid & 31;
    const int gid = lane >> 2, tig = lane & 3;
    const int wm = wid & 3, wn = wid >> 2;
    const int row0 = blockIdx.y * 128;
    const int BNout = SWIGLU ? 64 : 128;
    const int c0 = blockIdx.x * BNout;

    // staging descriptors: 4 A + 4 B 16B-chunks per thread per stage
    int aoff[4]; uint32_t asz[4]; uint32_t asw[4];
#pragma unroll
    for (int i = 0; i < 4; i++) {
        int f4 = tid + i * 256;
        int m = f4 >> 3, k4 = f4 & 7;
        asw[i] = (uint32_t)(m * 32 + ((k4 ^ (m & 7)) << 2)) * 4;
        int r = row0 + m;
        if (GATHER) {
            if (r < n) { aoff[i] = (rowlist[r] >> SHIFT) * lda + k4 * 4; asz[i] = 16; }
            else       { aoff[i] = 0; asz[i] = 0; }
        } else { aoff[i] = r * lda + k4 * 4; asz[i] = 16; }
    }
    int boff[4]; uint32_t bsw[4];
#pragma unroll
    for (int i = 0; i < 4; i++) {
        int f4 = tid + i * 256;
        int k = f4 >> 5, n4 = f4 & 31;
        int gcol;
        if (SWIGLU) {
            int t  = n4 >> 2;
            int up = (n4 >> 1) & 1;
            int ci = (n4 & 1) * 4;
            gcol = (up ? uoff : 0) + c0 + t * 8 + ci;
        } else {
            gcol = c0 + n4 * 4;
        }
        boff[i] = k * ldb + gcol;
        bsw[i] = (uint32_t)(4096 + k * 136 + n4 * 4) * 4;
    }

    float acc[2][8][4];
#pragma unroll
    for (int mt = 0; mt < 2; mt++)
#pragma unroll
        for (int j = 0; j < 8; j++)
#pragma unroll
            for (int q = 0; q < 4; q++) acc[mt][j][q] = 0.f;

    const int NC = K / 32;

#define ISSUE(ch)                                                            \
    {                                                                        \
        const uint32_t sb_ = sbase + (uint32_t)((ch) % 3) * STG_BYTES;       \
        const int ka_ = (ch) * 32;                                           \
        const int kb_ = (ch) * 32 * ldb;                                     \
        _Pragma("unroll")                                                    \
        for (int i = 0; i < 4; i++) cp16(sb_ + asw[i], A + aoff[i] + ka_, asz[i]); \
        _Pragma("unroll")                                                    \
        for (int i = 0; i < 4; i++) cp16(sb_ + bsw[i], B + boff[i] + kb_, 16u); \
    }

    ISSUE(0); CP_COMMIT();
    ISSUE(1); CP_COMMIT();

    for (int ch = 0; ch < NC; ch++) {
        CP_WAIT1();           // stage ch complete (newest 1 group may be pending)
        __syncthreads();      // all threads done reading stage (ch-1)
        if (ch + 2 < NC) { ISSUE(ch + 2); }   // writes stage (ch+2)%3 != ch%3
        CP_COMMIT();

        const uint32_t* As = smem + (ch % 3) * STG_WORDS;
        const uint32_t* Bs = As + 4096;
        const int msw = gid & 7;
#pragma unroll
        for (int ks = 0; ks < 4; ks++) {
            uint32_t a[2][4];
            const int c0w = ((ks * 2) ^ msw) << 2;
            const int c1w = ((ks * 2 + 1) ^ msw) << 2;
#pragma unroll
            for (int mt = 0; mt < 2; mt++) {
                const uint32_t* ap = As + (wm * 32 + mt * 16 + gid) * 32;
                a[mt][0] = ap[c0w + tig];
                a[mt][1] = ap[256 + c0w + tig];
                a[mt][2] = ap[c1w + tig];
                a[mt][3] = ap[256 + c1w + tig];
            }
            uint32_t b[8][2];
            const uint32_t* bp = Bs + (ks * 8 + tig) * 136 + wn * 64 + gid;
#pragma unroll
            for (int j = 0; j < 8; j++) {
                b[j][0] = bp[j * 8];
                b[j][1] = bp[544 + j * 8];
            }
#pragma unroll
            for (int mt = 0; mt < 2; mt++)
#pragma unroll
                for (int j = 0; j < 8; j++)
                    mma8(acc[mt][j], a[mt], b[j]);
        }
    }
#undef ISSUE

    // ---- epilogue ----
#pragma unroll
    for (int mt = 0; mt < 2; mt++) {
#pragma unroll
        for (int h = 0; h < 2; h++) {
            int r = row0 + wm * 32 + mt * 16 + gid + h * 8;
            bool valid = GATHER ? (r < n) : true;
            if (!valid) continue;
            int crow; float scale = 1.f;
            if (GATHER) {
                int slot = rowlist[r];
                crow = slot;
                if (SCALE) scale = g_slotw[slot];
            } else crow = r;
            float* cp = C + (long long)crow * ldc;
            if (SWIGLU) {
#pragma unroll
                for (int t2 = 0; t2 < 4; t2++) {
                    float g0 = acc[mt][t2 * 2][h * 2 + 0];
                    float g1 = acc[mt][t2 * 2][h * 2 + 1];
                    float u0 = acc[mt][t2 * 2 + 1][h * 2 + 0];
                    float u1 = acc[mt][t2 * 2 + 1][h * 2 + 1];
                    float2 o;
                    o.x = g0 / (1.f + expf(-g0)) * u0;
                    o.y = g1 / (1.f + expf(-g1)) * u1;
                    if (CVTOUT) {
                        o.x = __uint_as_float(f2tf(o.x));
                        o.y = __uint_as_float(f2tf(o.y));
                    }
                    *(float2*)(cp + c0 + (wn * 4 + t2) * 8 + tig * 2) = o;
                }
            } else {
#pragma unroll
                for (int j = 0; j < 8; j++) {
                    float2 o;
                    o.x = acc[mt][j][h * 2 + 0] * scale;
                    o.y = acc[mt][j][h * 2 + 1] * scale;
                    if (CVTOUT) {
                        o.x = __uint_as_float(f2tf(o.x));
                        o.y = __uint_as_float(f2tf(o.y));
                    }
                    *(float2*)(cp + c0 + (wn * 8 + j) * 8 + tig * 2) = o;
                }
            }
        }
    }
}

// ---------------- combine ----------------
__global__ void combine_kernel(float* __restrict__ out) {
    long long i = (long long)blockIdx.x * blockDim.x + threadIdx.x;
    const long long nf4 = (long long)T_TOK * DDIM / 4;
    if (i >= nf4) return;
    long long t = i / (DDIM / 4);
    int c = (int)(i % (DDIM / 4)) * 4;
    float4 o = *(float4*)(out + t * DDIM + c);
#pragma unroll
    for (int s = 0; s < KTOP; s++) {
        const float4 y = *(const float4*)(g_y_moe + ((t * KTOP + s) * (long long)DDIM) + c);
        o.x += y.x; o.y += y.y; o.z += y.z; o.w += y.w;
    }
    *(float4*)(out + t * DDIM + c) = o;
}

// ---------------- host ----------------
static float* sym_f(const void* symbol) {
    void* p = nullptr;
    cudaGetSymbolAddress(&p, symbol);
    return (float*)p;
}

static inline int cvt_grid(size_t n4) {
    size_t b = n4 / 2048;
    if (b > 8192) b = 8192;
    return (int)b;
}

extern "C" void kernel_launch(void* const* d_in, const int* in_sizes, int n_in,
                              void* d_out, int out_size) {
    (void)in_sizes; (void)n_in; (void)out_size;
    const float* x    = (const float*)d_in[0];
    const float* gw   = (const float*)d_in[1];
    const float* gb   = (const float*)d_in[2];
    const float* wgu  = (const float*)d_in[3];
    const float* wd   = (const float*)d_in[4];
    const float* wsgu = (const float*)d_in[5];
    const float* wsd  = (const float*)d_in[6];
    float* out = (float*)d_out;

    float* h_shared = sym_f(g_h_shared);
    float* h_moe    = sym_f(g_h_moe);
    float* y_moe    = sym_f(g_y_moe);
    float* x_t      = sym_f(g_x_t);
    float* wgu_t    = sym_f(g_wgu_t);
    float* wd_t     = sym_f(g_wd_t);
    float* wsgu_t   = sym_f(g_wsgu_t);
    float* wsd_t    = sym_f(g_wsd_t);

    cudaFuncSetAttribute(tgemm<false, true,  false, 0, true >, cudaFuncAttributeMaxDynamicSharedMemorySize, SM_BYTES);
    cudaFuncSetAttribute(tgemm<false, false, false, 0, false>, cudaFuncAttributeMaxDynamicSharedMemorySize, SM_BYTES);
    cudaFuncSetAttribute(tgemm<true,  true,  false, 2, true >, cudaFuncAttributeMaxDynamicSharedMemorySize, SM_BYTES);
    cudaFuncSetAttribute(tgemm<true,  false, true,  0, false>, cudaFuncAttributeMaxDynamicSharedMemorySize, SM_BYTES);

    // tf32 pre-conversion passes (all sizes are multiples of 2048 float4s)
    size_t n_x    = (size_t)T_TOK * DDIM / 4;
    size_t n_wgu  = (size_t)NEXP * DDIM * 2 * IDIM / 4;
    size_t n_wd   = (size_t)NEXP * IDIM * DDIM / 4;
    size_t n_wsgu = (size_t)DDIM * 2 * SIDIM / 4;
    size_t n_wsd  = (size_t)SIDIM * DDIM / 4;
    cvt_kernel<<<cvt_grid(n_x),    256>>>((const float4*)x,    (float4*)x_t,    (int)n_x);
    cvt_kernel<<<cvt_grid(n_wgu),  256>>>((const float4*)wgu,  (float4*)wgu_t,  (int)n_wgu);
    cvt_kernel<<<cvt_grid(n_wd),   256>>>((const float4*)wd,   (float4*)wd_t,   (int)n_wd);
    cvt_kernel<<<cvt_grid(n_wsgu), 256>>>((const float4*)wsgu, (float4*)wsgu_t, (int)n_wsgu);
    cvt_kernel<<<cvt_grid(n_wsd),  256>>>((const float4*)wsd,  (float4*)wsd_t,  (int)n_wsd);

    init_kernel<<<1, 32>>>();
    router_kernel<<<T_TOK / 8, 256>>>(x, gw, gb);

    // shared gate_up + SwiGLU: x_t[T,D] @ wsgu_t[D,2SI] -> h_shared[T,SI] (tf32-rounded)
    tgemm<false, true, false, 0, true>
        <<<dim3(SIDIM / 64, T_TOK / 128, 1), 256, SM_BYTES>>>(
            x_t, wsgu_t, h_shared, DDIM, DDIM, 2 * SIDIM, SIDIM, 0, SIDIM);

    // shared down: h_shared @ wsd_t -> out (dense write covers poison)
    tgemm<false, false, false, 0, false>
        <<<dim3(DDIM / 128, T_TOK / 128, 1), 256, SM_BYTES>>>(
            h_shared, wsd_t, out, SIDIM, SIDIM, DDIM, DDIM, 0, 0);

    // routed gate_up + SwiGLU (gather tokens): x_t @ wgu_t[e] -> h_moe[slot, I] (tf32-rounded)
    tgemm<true, true, false, 2, true>
        <<<dim3(IDIM / 64, T_TOK / 128, NEXP), 256, SM_BYTES>>>(
            x_t, wgu_t, h_moe, DDIM, DDIM, 2 * IDIM, IDIM,
            (long long)DDIM * 2 * IDIM, IDIM);

    // routed down (gather slots, scale): h_moe @ wd_t[e] -> y_moe[slot, D]
    tgemm<true, false, true, 0, false>
        <<<dim3(DDIM / 128, T_TOK / 128, NEXP), 256, SM_BYTES>>>(
            h_moe, wd_t, y_moe, IDIM, IDIM, DDIM, DDIM,
            (long long)IDIM * DDIM, 0);

    combine_kernel<<<(T_TOK * DDIM / 4 + 255) / 256, 256>>>(out);
}

// round 9
// speedup vs baseline: 1.6207x; 1.1033x over previous
#include <cuda_runtime.h>
#include <math.h>
#include <stdint.h>

// Problem constants
#define T_TOK 2048
#define DDIM  2048
#define NEXP  16
#define IDIM  1024
#define SIDIM 2048
#define KTOP  4

// ---------------- scratch (__device__ globals, allocation-free) ----------------
__device__ float g_h_shared[(size_t)T_TOK * SIDIM];
__device__ float g_h_moe[(size_t)T_TOK * KTOP * IDIM];
__device__ float g_y_moe[(size_t)T_TOK * KTOP * DDIM];
__device__ int   g_counts[NEXP];
__device__ int   g_rows[NEXP * T_TOK];
__device__ float g_slotw[T_TOK * KTOP];
// tf32-preconverted operands
__device__ float g_x_t[(size_t)T_TOK * DDIM];
__device__ float g_wgu_t[(size_t)NEXP * DDIM * 2 * IDIM];
__device__ float g_wd_t[(size_t)NEXP * IDIM * DDIM];
__device__ float g_wsgu_t[(size_t)DDIM * 2 * SIDIM];
__device__ float g_wsd_t[(size_t)SIDIM * DDIM];

// ---------------- helpers ----------------
__device__ __forceinline__ uint32_t f2tf(float f) {
    uint32_t r;
    asm("cvt.rna.tf32.f32 %0, %1;" : "=r"(r) : "f"(f));
    return r;
}
__device__ __forceinline__ uint4 cvt4(float4 v) {
    uint4 t;
    t.x = f2tf(v.x); t.y = f2tf(v.y); t.z = f2tf(v.z); t.w = f2tf(v.w);
    return t;
}
__device__ __forceinline__ void mma8(float c[4], const uint32_t a[4], const uint32_t b[2]) {
    asm volatile(
        "mma.sync.aligned.m16n8k8.row.col.f32.tf32.tf32.f32 "
        "{%0,%1,%2,%3}, {%4,%5,%6,%7}, {%8,%9}, {%0,%1,%2,%3};"
        : "+f"(c[0]), "+f"(c[1]), "+f"(c[2]), "+f"(c[3])
        : "r"(a[0]), "r"(a[1]), "r"(a[2]), "r"(a[3]), "r"(b[0]), "r"(b[1]));
}
__device__ __forceinline__ uint32_t smem_u32(const void* p) {
    uint32_t a;
    asm("{ .reg .u64 t; cvta.to.shared.u64 t, %1; cvt.u32.u64 %0, t; }" : "=r"(a) : "l"(p));
    return a;
}
__device__ __forceinline__ void cp16(uint32_t saddr, const void* gptr, uint32_t sz) {
    asm volatile("cp.async.cg.shared.global [%0], [%1], 16, %2;"
                 :: "r"(saddr), "l"(gptr), "r"(sz) : "memory");
}
#define CP_COMMIT() asm volatile("cp.async.commit_group;" ::: "memory")
#define CP_WAIT1()  asm volatile("cp.async.wait_group 1;" ::: "memory")

// smem stage: A 4096 words + B 4352 words (32 rows x 136 incl pad) = 8448 words
#define STG_WORDS 8448
#define STG_BYTES (STG_WORDS * 4)          // 33792
#define SM_BYTES  (3 * STG_BYTES)          // 101376

// ---------------- conversion kernel: dst = tf32_rna(src) ----------------
__global__ void cvt_kernel(const float4* __restrict__ src, float4* __restrict__ dst, int n4) {
    const long long step = (long long)gridDim.x * 2048;
    for (long long base = (long long)blockIdx.x * 2048 + threadIdx.x; base < n4; base += step) {
        float4 v[8];
#pragma unroll
        for (int k = 0; k < 8; k++) v[k] = src[base + k * 256];
        uint4 t[8];
#pragma unroll
        for (int k = 0; k < 8; k++) t[k] = cvt4(v[k]);
#pragma unroll
        for (int k = 0; k < 8; k++) dst[base + k * 256] = *(float4*)&t[k];
    }
}

// ---------------- init + router ----------------
__global__ void init_kernel() {
    if (threadIdx.x < NEXP) g_counts[threadIdx.x] = 0;
}

__global__ void router_kernel(const float* __restrict__ x,
                              const float* __restrict__ gw,
                              const float* __restrict__ gb) {
    int wid  = threadIdx.x >> 5;
    int lane = threadIdx.x & 31;
    int t = blockIdx.x * (blockDim.x >> 5) + wid;
    if (t >= T_TOK) return;

    float acc[NEXP];
#pragma unroll
    for (int e = 0; e < NEXP; e++) acc[e] = 0.f;
    const float* xr = x + (size_t)t * DDIM;
    for (int j = lane; j < DDIM; j += 32) {
        float xv = xr[j];
#pragma unroll
        for (int e = 0; e < NEXP; e++) acc[e] += xv * gw[e * DDIM + j];
    }
#pragma unroll
    for (int e = 0; e < NEXP; e++) {
#pragma unroll
        for (int off = 16; off > 0; off >>= 1)
            acc[e] += __shfl_xor_sync(0xffffffffu, acc[e], off);
    }
    float mx = acc[0];
#pragma unroll
    for (int e = 1; e < NEXP; e++) mx = fmaxf(mx, acc[e]);
    float p[NEXP]; float sum = 0.f;
#pragma unroll
    for (int e = 0; e < NEXP; e++) { p[e] = expf(acc[e] - mx); sum += p[e]; }
    float inv = 1.f / sum;
#pragma unroll
    for (int e = 0; e < NEXP; e++) p[e] *= inv;
    float bmin = gb[0];
#pragma unroll
    for (int e = 1; e < NEXP; e++) bmin = fminf(bmin, gb[e]);
    float sel[NEXP];
#pragma unroll
    for (int e = 0; e < NEXP; e++) sel[e] = p[e] + (gb[e] - bmin);
    int idx[KTOP]; float w[KTOP]; float wsum = 0.f;
#pragma unroll
    for (int s = 0; s < KTOP; s++) {
        int best = 0; float bv = sel[0];
#pragma unroll
        for (int e = 1; e < NEXP; e++) { if (sel[e] > bv) { bv = sel[e]; best = e; } }
        idx[s] = best; w[s] = p[best]; wsum += p[best];
        sel[best] = -1e30f;
    }
    float invw = 1.f / wsum;
    if (lane == 0) {
#pragma unroll
        for (int s = 0; s < KTOP; s++) {
            int slot = t * KTOP + s;
            g_slotw[slot] = w[s] * invw;
            int pos = atomicAdd(&g_counts[idx[s]], 1);
            g_rows[idx[s] * T_TOK + pos] = slot;
        }
    }
}

// ---------------- tf32 mma.sync GEMM (cp.async 3-stage, single-barrier) ----------------
template <bool GATHER, bool SWIGLU, bool SCALE, int SHIFT, bool CVTOUT>
__global__ void __launch_bounds__(256, 2)
tgemm(const float* __restrict__ A, const float* __restrict__ Bmat,
      float* __restrict__ C, int K, int lda, int ldb, int ldc,
      long long bstride, int uoff)
{
    int n = 0x7fffffff;
    const int* rowlist = nullptr;
    const float* B = Bmat;
    if (GATHER) {
        int e = blockIdx.z;
        n = g_counts[e];
        if ((int)(blockIdx.y * 128) >= n) return;
        rowlist = g_rows + e * T_TOK;
        B = Bmat + (long long)e * bstride;
    }

    extern __shared__ uint32_t smem[];
    const uint32_t sbase = smem_u32(smem);
    const int tid = threadIdx.x;
    const int wid = tid >> 5, lane = tid & 31;
    const int gid = lane >> 2, tig = lane & 3;
    const int wm = wid & 3, wn = wid >> 2;
    const int row0 = blockIdx.y * 128;
    const int BNout = SWIGLU ? 64 : 128;
    const int c0 = blockIdx.x * BNout;

    // staging descriptors: 4 A + 4 B 16B-chunks per thread per stage
    int aoff[4]; uint32_t asz[4]; uint32_t asw[4];
#pragma unroll
    for (int i = 0; i < 4; i++) {
        int f4 = tid + i * 256;
        int m = f4 >> 3, k4 = f4 & 7;
        asw[i] = (uint32_t)(m * 32 + ((k4 ^ (m & 7)) << 2)) * 4;
        int r = row0 + m;
        if (GATHER) {
            if (r < n) { aoff[i] = (rowlist[r] >> SHIFT) * lda + k4 * 4; asz[i] = 16; }
            else       { aoff[i] = 0; asz[i] = 0; }
        } else { aoff[i] = r * lda + k4 * 4; asz[i] = 16; }
    }
    int boff[4]; uint32_t bsw[4];
#pragma unroll
    for (int i = 0; i < 4; i++) {
        int f4 = tid + i * 256;
        int k = f4 >> 5, n4 = f4 & 31;
        int gcol;
        if (SWIGLU) {
            int t  = n4 >> 2;
            int up = (n4 >> 1) & 1;
            int ci = (n4 & 1) * 4;
            gcol = (up ? uoff : 0) + c0 + t * 8 + ci;
        } else {
            gcol = c0 + n4 * 4;
        }
        boff[i] = k * ldb + gcol;
        bsw[i] = (uint32_t)(4096 + k * 136 + n4 * 4) * 4;
    }

    float acc[2][8][4];
#pragma unroll
    for (int mt = 0; mt < 2; mt++)
#pragma unroll
        for (int j = 0; j < 8; j++)
#pragma unroll
            for (int q = 0; q < 4; q++) acc[mt][j][q] = 0.f;

    const int NC = K / 32;

#define ISSUE(ch)                                                            \
    {                                                                        \
        const uint32_t sb_ = sbase + (uint32_t)((ch) % 3) * STG_BYTES;       \
        const int ka_ = (ch) * 32;                                           \
        const int kb_ = (ch) * 32 * ldb;                                     \
        _Pragma("unroll")                                                    \
        for (int i = 0; i < 4; i++) cp16(sb_ + asw[i], A + aoff[i] + ka_, asz[i]); \
        _Pragma("unroll")                                                    \
        for (int i = 0; i < 4; i++) cp16(sb_ + bsw[i], B + boff[i] + kb_, 16u); \
    }

    ISSUE(0); CP_COMMIT();
    ISSUE(1); CP_COMMIT();

    for (int ch = 0; ch < NC; ch++) {
        CP_WAIT1();
        __syncthreads();
        if (ch + 2 < NC) { ISSUE(ch + 2); }
        CP_COMMIT();

        const uint32_t* As = smem + (ch % 3) * STG_WORDS;
        const uint32_t* Bs = As + 4096;
        const int msw = gid & 7;
#pragma unroll
        for (int ks = 0; ks < 4; ks++) {
            uint32_t a[2][4];
            const int c0w = ((ks * 2) ^ msw) << 2;
            const int c1w = ((ks * 2 + 1) ^ msw) << 2;
#pragma unroll
            for (int mt = 0; mt < 2; mt++) {
                const uint32_t* ap = As + (wm * 32 + mt * 16 + gid) * 32;
                a[mt][0] = ap[c0w + tig];
                a[mt][1] = ap[256 + c0w + tig];
                a[mt][2] = ap[c1w + tig];
                a[mt][3] = ap[256 + c1w + tig];
            }
            uint32_t b[8][2];
            const uint32_t* bp = Bs + (ks * 8 + tig) * 136 + wn * 64 + gid;
#pragma unroll
            for (int j = 0; j < 8; j++) {
                b[j][0] = bp[j * 8];
                b[j][1] = bp[544 + j * 8];
            }
#pragma unroll
            for (int mt = 0; mt < 2; mt++)
#pragma unroll
                for (int j = 0; j < 8; j++)
                    mma8(acc[mt][j], a[mt], b[j]);
        }
    }
#undef ISSUE

    // ---- epilogue ----
#pragma unroll
    for (int mt = 0; mt < 2; mt++) {
#pragma unroll
        for (int h = 0; h < 2; h++) {
            int r = row0 + wm * 32 + mt * 16 + gid + h * 8;
            bool valid = GATHER ? (r < n) : true;
            if (!valid) continue;
            int crow; float scale = 1.f;
            if (GATHER) {
                int slot = rowlist[r];
                crow = slot;
                if (SCALE) scale = g_slotw[slot];
            } else crow = r;
            float* cp = C + (long long)crow * ldc;
            if (SWIGLU) {
#pragma unroll
                for (int t2 = 0; t2 < 4; t2++) {
                    float g0 = acc[mt][t2 * 2][h * 2 + 0];
                    float g1 = acc[mt][t2 * 2][h * 2 + 1];
                    float u0 = acc[mt][t2 * 2 + 1][h * 2 + 0];
                    float u1 = acc[mt][t2 * 2 + 1][h * 2 + 1];
                    float2 o;
                    o.x = g0 / (1.f + expf(-g0)) * u0;
                    o.y = g1 / (1.f + expf(-g1)) * u1;
                    if (CVTOUT) {
                        o.x = __uint_as_float(f2tf(o.x));
                        o.y = __uint_as_float(f2tf(o.y));
                    }
                    *(float2*)(cp + c0 + (wn * 4 + t2) * 8 + tig * 2) = o;
                }
            } else {
#pragma unroll
                for (int j = 0; j < 8; j++) {
                    float2 o;
                    o.x = acc[mt][j][h * 2 + 0] * scale;
                    o.y = acc[mt][j][h * 2 + 1] * scale;
                    if (CVTOUT) {
                        o.x = __uint_as_float(f2tf(o.x));
                        o.y = __uint_as_float(f2tf(o.y));
                    }
                    *(float2*)(cp + c0 + (wn * 8 + j) * 8 + tig * 2) = o;
                }
            }
        }
    }
}

// ---------------- combine ----------------
__global__ void combine_kernel(float* __restrict__ out) {
    long long i = (long long)blockIdx.x * blockDim.x + threadIdx.x;
    const long long nf4 = (long long)T_TOK * DDIM / 4;
    if (i >= nf4) return;
    long long t = i / (DDIM / 4);
    int c = (int)(i % (DDIM / 4)) * 4;
    float4 o = *(float4*)(out + t * DDIM + c);
#pragma unroll
    for (int s = 0; s < KTOP; s++) {
        const float4 y = *(const float4*)(g_y_moe + ((t * KTOP + s) * (long long)DDIM) + c);
        o.x += y.x; o.y += y.y; o.z += y.z; o.w += y.w;
    }
    *(float4*)(out + t * DDIM + c) = o;
}

// ---------------- host ----------------
static float* sym_f(const void* symbol) {
    void* p = nullptr;
    cudaGetSymbolAddress(&p, symbol);
    return (float*)p;
}

static inline int cvt_grid(size_t n4) {
    size_t b = n4 / 2048;
    if (b > 8192) b = 8192;
    return (int)b;
}

extern "C" void kernel_launch(void* const* d_in, const int* in_sizes, int n_in,
                              void* d_out, int out_size) {
    (void)in_sizes; (void)n_in; (void)out_size;
    const float* x    = (const float*)d_in[0];
    const float* gw   = (const float*)d_in[1];
    const float* gb   = (const float*)d_in[2];
    const float* wgu  = (const float*)d_in[3];
    const float* wd   = (const float*)d_in[4];
    const float* wsgu = (const float*)d_in[5];
    const float* wsd  = (const float*)d_in[6];
    float* out = (float*)d_out;

    float* h_shared = sym_f(g_h_shared);
    float* h_moe    = sym_f(g_h_moe);
    float* y_moe    = sym_f(g_y_moe);
    float* x_t      = sym_f(g_x_t);
    float* wgu_t    = sym_f(g_wgu_t);
    float* wd_t     = sym_f(g_wd_t);
    float* wsgu_t   = sym_f(g_wsgu_t);
    float* wsd_t    = sym_f(g_wsd_t);

    cudaFuncSetAttribute(tgemm<false, true,  false, 0, true >, cudaFuncAttributeMaxDynamicSharedMemorySize, SM_BYTES);
    cudaFuncSetAttribute(tgemm<false, false, false, 0, false>, cudaFuncAttributeMaxDynamicSharedMemorySize, SM_BYTES);
    cudaFuncSetAttribute(tgemm<true,  true,  false, 2, true >, cudaFuncAttributeMaxDynamicSharedMemorySize, SM_BYTES);
    cudaFuncSetAttribute(tgemm<true,  false, true,  0, false>, cudaFuncAttributeMaxDynamicSharedMemorySize, SM_BYTES);

    size_t n_x    = (size_t)T_TOK * DDIM / 4;
    size_t n_wgu  = (size_t)NEXP * DDIM * 2 * IDIM / 4;
    size_t n_wd   = (size_t)NEXP * IDIM * DDIM / 4;
    size_t n_wsgu = (size_t)DDIM * 2 * SIDIM / 4;
    size_t n_wsd  = (size_t)SIDIM * DDIM / 4;

    // Two-track fork/join (graph-capture-legal: kernel launches + event deps only).
    // Handles are created fresh each call (host-side only; deterministic work).
    cudaStream_t s2 = 0;
    cudaEvent_t evFork = 0, evX = 0, evWd = 0, evB = 0;
    cudaStreamCreateWithFlags(&s2, cudaStreamNonBlocking);
    cudaEventCreateWithFlags(&evFork, cudaEventDisableTiming);
    cudaEventCreateWithFlags(&evX,    cudaEventDisableTiming);
    cudaEventCreateWithFlags(&evWd,   cudaEventDisableTiming);
    cudaEventCreateWithFlags(&evB,    cudaEventDisableTiming);

    // fork s2 from the capture (default) stream
    cudaEventRecord(evFork, 0);
    cudaStreamWaitEvent(s2, evFork, 0);

    // ---- Track A (default stream): x cvt, wd cvt, shared-expert chain ----
    cvt_kernel<<<cvt_grid(n_x), 256>>>((const float4*)x, (float4*)x_t, (int)n_x);
    cudaEventRecord(evX, 0);
    cvt_kernel<<<cvt_grid(n_wd), 256>>>((const float4*)wd, (float4*)wd_t, (int)n_wd);
    cudaEventRecord(evWd, 0);
    cvt_kernel<<<cvt_grid(n_wsgu), 256>>>((const float4*)wsgu, (float4*)wsgu_t, (int)n_wsgu);
    // shared gate_up + SwiGLU: x_t @ wsgu_t -> h_shared (tf32-rounded)
    tgemm<false, true, false, 0, true>
        <<<dim3(SIDIM / 64, T_TOK / 128, 1), 256, SM_BYTES>>>(
            x_t, wsgu_t, h_shared, DDIM, DDIM, 2 * SIDIM, SIDIM, 0, SIDIM);
    cvt_kernel<<<cvt_grid(n_wsd), 256>>>((const float4*)wsd, (float4*)wsd_t, (int)n_wsd);
    // shared down: h_shared @ wsd_t -> out (dense write covers poison)
    tgemm<false, false, false, 0, false>
        <<<dim3(DDIM / 128, T_TOK / 128, 1), 256, SM_BYTES>>>(
            h_shared, wsd_t, out, SIDIM, SIDIM, DDIM, DDIM, 0, 0);

    // ---- Track B (s2): router + routed-expert chain ----
    init_kernel<<<1, 32, 0, s2>>>();
    router_kernel<<<T_TOK / 8, 256, 0, s2>>>(x, gw, gb);
    cvt_kernel<<<cvt_grid(n_wgu), 256, 0, s2>>>((const float4*)wgu, (float4*)wgu_t, (int)n_wgu);
    cudaStreamWaitEvent(s2, evX, 0);
    // routed gate_up + SwiGLU (gather tokens): x_t @ wgu_t[e] -> h_moe (tf32-rounded)
    tgemm<true, true, false, 2, true>
        <<<dim3(IDIM / 64, T_TOK / 128, NEXP), 256, SM_BYTES, s2>>>(
            x_t, wgu_t, h_moe, DDIM, DDIM, 2 * IDIM, IDIM,
            (long long)DDIM * 2 * IDIM, IDIM);
    cudaStreamWaitEvent(s2, evWd, 0);
    // routed down (gather slots, scale): h_moe @ wd_t[e] -> y_moe
    tgemm<true, false, true, 0, false>
        <<<dim3(DDIM / 128, T_TOK / 128, NEXP), 256, SM_BYTES, s2>>>(
            h_moe, wd_t, y_moe, IDIM, IDIM, DDIM, DDIM,
            (long long)IDIM * DDIM, 0);
    cudaEventRecord(evB, s2);

    // ---- join on default stream ----
    cudaStreamWaitEvent(0, evB, 0);
    combine_kernel<<<(T_TOK * DDIM / 4 + 255) / 256, 256>>>(out);
    // Handles intentionally not destroyed: destruction during capture risks
    // aborting the capture; leaked host-side handles only (few calls total).
}

// round 10
// speedup vs baseline: 1.7423x; 1.0750x over previous
#include <cuda_runtime.h>
#include <math.h>
#include <stdint.h>

// Problem constants
#define T_TOK 2048
#define DDIM  2048
#define NEXP  16
#define IDIM  1024
#define SIDIM 2048
#define KTOP  4

// ---------------- scratch (__device__ globals, allocation-free) ----------------
__device__ float g_h_shared[(size_t)T_TOK * SIDIM];
__device__ float g_h_moe[(size_t)T_TOK * KTOP * IDIM];
__device__ float g_y_moe[(size_t)T_TOK * KTOP * DDIM];
__device__ int   g_counts[NEXP];
__device__ int   g_rows[NEXP * T_TOK];
__device__ float g_slotw[T_TOK * KTOP];
__device__ float g_x_t[(size_t)T_TOK * DDIM];   // tf32-rounded x

// ---------------- helpers ----------------
__device__ __forceinline__ uint32_t f2tf(float f) {
    uint32_t r;
    asm("cvt.rna.tf32.f32 %0, %1;" : "=r"(r) : "f"(f));
    return r;
}
__device__ __forceinline__ uint4 cvt4(float4 v) {
    uint4 t;
    t.x = f2tf(v.x); t.y = f2tf(v.y); t.z = f2tf(v.z); t.w = f2tf(v.w);
    return t;
}
__device__ __forceinline__ void mma8(float c[4], const uint32_t a[4], const uint32_t b[2]) {
    asm volatile(
        "mma.sync.aligned.m16n8k8.row.col.f32.tf32.tf32.f32 "
        "{%0,%1,%2,%3}, {%4,%5,%6,%7}, {%8,%9}, {%0,%1,%2,%3};"
        : "+f"(c[0]), "+f"(c[1]), "+f"(c[2]), "+f"(c[3])
        : "r"(a[0]), "r"(a[1]), "r"(a[2]), "r"(a[3]), "r"(b[0]), "r"(b[1]));
}
__device__ __forceinline__ uint32_t smem_u32(const void* p) {
    uint32_t a;
    asm("{ .reg .u64 t; cvta.to.shared.u64 t, %1; cvt.u32.u64 %0, t; }" : "=r"(a) : "l"(p));
    return a;
}
__device__ __forceinline__ void cp16(uint32_t saddr, const void* gptr, uint32_t sz) {
    asm volatile("cp.async.cg.shared.global [%0], [%1], 16, %2;"
                 :: "r"(saddr), "l"(gptr), "r"(sz) : "memory");
}
#define CP_COMMIT() asm volatile("cp.async.commit_group;" ::: "memory")
#define CP_WAIT1()  asm volatile("cp.async.wait_group 1;" ::: "memory")

// smem stage: A 4096 words + B 4352 words (32 rows x 136 incl pad) = 8448 words
#define STG_WORDS 8448
#define STG_BYTES (STG_WORDS * 4)          // 33792
#define SM_BYTES  (3 * STG_BYTES)          // 101376

// ---------------- conversion kernel (x only): dst = tf32_rna(src) ----------------
__global__ void cvt_kernel(const float4* __restrict__ src, float4* __restrict__ dst, int n4) {
    const long long step = (long long)gridDim.x * 2048;
    for (long long base = (long long)blockIdx.x * 2048 + threadIdx.x; base < n4; base += step) {
        float4 v[8];
#pragma unroll
        for (int k = 0; k < 8; k++) v[k] = src[base + k * 256];
        uint4 t[8];
#pragma unroll
        for (int k = 0; k < 8; k++) t[k] = cvt4(v[k]);
#pragma unroll
        for (int k = 0; k < 8; k++) dst[base + k * 256] = *(float4*)&t[k];
    }
}

// ---------------- init + router ----------------
__global__ void init_kernel() {
    if (threadIdx.x < NEXP) g_counts[threadIdx.x] = 0;
}

__global__ void router_kernel(const float* __restrict__ x,
                              const float* __restrict__ gw,
                              const float* __restrict__ gb) {
    int wid  = threadIdx.x >> 5;
    int lane = threadIdx.x & 31;
    int t = blockIdx.x * (blockDim.x >> 5) + wid;
    if (t >= T_TOK) return;

    float acc[NEXP];
#pragma unroll
    for (int e = 0; e < NEXP; e++) acc[e] = 0.f;
    const float* xr = x + (size_t)t * DDIM;
    for (int j = lane; j < DDIM; j += 32) {
        float xv = xr[j];
#pragma unroll
        for (int e = 0; e < NEXP; e++) acc[e] += xv * gw[e * DDIM + j];
    }
#pragma unroll
    for (int e = 0; e < NEXP; e++) {
#pragma unroll
        for (int off = 16; off > 0; off >>= 1)
            acc[e] += __shfl_xor_sync(0xffffffffu, acc[e], off);
    }
    float mx = acc[0];
#pragma unroll
    for (int e = 1; e < NEXP; e++) mx = fmaxf(mx, acc[e]);
    float p[NEXP]; float sum = 0.f;
#pragma unroll
    for (int e = 0; e < NEXP; e++) { p[e] = expf(acc[e] - mx); sum += p[e]; }
    float inv = 1.f / sum;
#pragma unroll
    for (int e = 0; e < NEXP; e++) p[e] *= inv;
    float bmin = gb[0];
#pragma unroll
    for (int e = 1; e < NEXP; e++) bmin = fminf(bmin, gb[e]);
    float sel[NEXP];
#pragma unroll
    for (int e = 0; e < NEXP; e++) sel[e] = p[e] + (gb[e] - bmin);
    int idx[KTOP]; float w[KTOP]; float wsum = 0.f;
#pragma unroll
    for (int s = 0; s < KTOP; s++) {
        int best = 0; float bv = sel[0];
#pragma unroll
        for (int e = 1; e < NEXP; e++) { if (sel[e] > bv) { bv = sel[e]; best = e; } }
        idx[s] = best; w[s] = p[best]; wsum += p[best];
        sel[best] = -1e30f;
    }
    float invw = 1.f / wsum;
    if (lane == 0) {
#pragma unroll
        for (int s = 0; s < KTOP; s++) {
            int slot = t * KTOP + s;
            g_slotw[slot] = w[s] * invw;
            int pos = atomicAdd(&g_counts[idx[s]], 1);
            g_rows[idx[s] * T_TOK + pos] = slot;
        }
    }
}

// ---------------- tf32 mma.sync GEMM ----------------
// A: pre-rounded tf32-in-fp32, staged via cp.async (3-stage).
// B: RAW fp32 weights, staged via LDG.128 -> cvt.rna.tf32 -> STS.128 two chunks
//    ahead (STS drained by the two intervening __syncthreads).
template <bool GATHER, bool SWIGLU, bool SCALE, int SHIFT, bool CVTOUT>
__global__ void __launch_bounds__(256, 2)
tgemm(const float* __restrict__ A, const float* __restrict__ Bmat,
      float* __restrict__ C, int K, int lda, int ldb, int ldc,
      long long bstride, int uoff)
{
    int n = 0x7fffffff;
    const int* rowlist = nullptr;
    const float* B = Bmat;
    if (GATHER) {
        int e = blockIdx.z;
        n = g_counts[e];
        if ((int)(blockIdx.y * 128) >= n) return;
        rowlist = g_rows + e * T_TOK;
        B = Bmat + (long long)e * bstride;
    }

    extern __shared__ uint32_t smem[];
    const uint32_t sbase = smem_u32(smem);
    const int tid = threadIdx.x;
    const int wid = tid >> 5, lane = tid & 31;
    const int gid = lane >> 2, tig = lane & 3;
    const int wm = wid & 3, wn = wid >> 2;
    const int row0 = blockIdx.y * 128;
    const int BNout = SWIGLU ? 64 : 128;
    const int c0 = blockIdx.x * BNout;

    // A staging descriptors: 4 16B cp.async chunks per thread per stage
    int aoff[4]; uint32_t asz[4]; uint32_t asw[4];
#pragma unroll
    for (int i = 0; i < 4; i++) {
        int f4 = tid + i * 256;
        int m = f4 >> 3, k4 = f4 & 7;
        asw[i] = (uint32_t)(m * 32 + ((k4 ^ (m & 7)) << 2)) * 4;
        int r = row0 + m;
        if (GATHER) {
            if (r < n) { aoff[i] = (rowlist[r] >> SHIFT) * lda + k4 * 4; asz[i] = 16; }
            else       { aoff[i] = 0; asz[i] = 0; }
        } else { aoff[i] = r * lda + k4 * 4; asz[i] = 16; }
    }
    // B staging descriptors: 4 float4 LDG->cvt->STS per thread per stage
    int boff[4]; uint32_t bsw[4];
#pragma unroll
    for (int i = 0; i < 4; i++) {
        int f4 = tid + i * 256;
        int k = f4 >> 5, n4 = f4 & 31;
        int gcol;
        if (SWIGLU) {
            int t  = n4 >> 2;
            int up = (n4 >> 1) & 1;
            int ci = (n4 & 1) * 4;
            gcol = (up ? uoff : 0) + c0 + t * 8 + ci;
        } else {
            gcol = c0 + n4 * 4;
        }
        boff[i] = k * ldb + gcol;
        bsw[i] = (uint32_t)(4096 + k * 136 + n4 * 4) * 4;
    }

    float acc[2][8][4];
#pragma unroll
    for (int mt = 0; mt < 2; mt++)
#pragma unroll
        for (int j = 0; j < 8; j++)
#pragma unroll
            for (int q = 0; q < 4; q++) acc[mt][j][q] = 0.f;

    const int NC = K / 32;

#define ISSUE_A(ch)                                                          \
    {                                                                        \
        const uint32_t sb_ = sbase + (uint32_t)((ch) % 3) * STG_BYTES;       \
        const int ka_ = (ch) * 32;                                           \
        _Pragma("unroll")                                                    \
        for (int i = 0; i < 4; i++) cp16(sb_ + asw[i], A + aoff[i] + ka_, asz[i]); \
    }
#define STAGE_B(ch)                                                          \
    {                                                                        \
        char* sb_ = (char*)smem + ((ch) % 3) * STG_BYTES;                    \
        const int kb_ = (ch) * 32 * ldb;                                     \
        float4 v0 = *(const float4*)(B + boff[0] + kb_);                     \
        float4 v1 = *(const float4*)(B + boff[1] + kb_);                     \
        float4 v2 = *(const float4*)(B + boff[2] + kb_);                     \
        float4 v3 = *(const float4*)(B + boff[3] + kb_);                     \
        uint4 t0 = cvt4(v0); *(uint4*)(sb_ + bsw[0]) = t0;                   \
        uint4 t1 = cvt4(v1); *(uint4*)(sb_ + bsw[1]) = t1;                   \
        uint4 t2 = cvt4(v2); *(uint4*)(sb_ + bsw[2]) = t2;                   \
        uint4 t3 = cvt4(v3); *(uint4*)(sb_ + bsw[3]) = t3;                   \
    }

    ISSUE_A(0); CP_COMMIT();
    STAGE_B(0);
    ISSUE_A(1); CP_COMMIT();
    STAGE_B(1);

    for (int ch = 0; ch < NC; ch++) {
        CP_WAIT1();           // A-stage ch complete (newest 1 group may be pending)
        __syncthreads();      // drains STS (B-stages ch, ch+1 visible); readers of ch-1 done
        if (ch + 2 < NC) {
            ISSUE_A(ch + 2); CP_COMMIT();
            STAGE_B(ch + 2);
        } else {
            CP_COMMIT();      // keep group bookkeeping consistent
        }

        const uint32_t* As = smem + (ch % 3) * STG_WORDS;
        const uint32_t* Bs = As + 4096;
        const int msw = gid & 7;
#pragma unroll
        for (int ks = 0; ks < 4; ks++) {
            uint32_t a[2][4];
            const int c0w = ((ks * 2) ^ msw) << 2;
            const int c1w = ((ks * 2 + 1) ^ msw) << 2;
#pragma unroll
            for (int mt = 0; mt < 2; mt++) {
                const uint32_t* ap = As + (wm * 32 + mt * 16 + gid) * 32;
                a[mt][0] = ap[c0w + tig];
                a[mt][1] = ap[256 + c0w + tig];
                a[mt][2] = ap[c1w + tig];
                a[mt][3] = ap[256 + c1w + tig];
            }
            uint32_t b[8][2];
            const uint32_t* bp = Bs + (ks * 8 + tig) * 136 + wn * 64 + gid;
#pragma unroll
            for (int j = 0; j < 8; j++) {
                b[j][0] = bp[j * 8];
                b[j][1] = bp[544 + j * 8];
            }
#pragma unroll
            for (int mt = 0; mt < 2; mt++)
#pragma unroll
                for (int j = 0; j < 8; j++)
                    mma8(acc[mt][j], a[mt], b[j]);
        }
    }
#undef ISSUE_A
#undef STAGE_B

    // ---- epilogue ----
#pragma unroll
    for (int mt = 0; mt < 2; mt++) {
#pragma unroll
        for (int h = 0; h < 2; h++) {
            int r = row0 + wm * 32 + mt * 16 + gid + h * 8;
            bool valid = GATHER ? (r < n) : true;
            if (!valid) continue;
            int crow; float scale = 1.f;
            if (GATHER) {
                int slot = rowlist[r];
                crow = slot;
                if (SCALE) scale = g_slotw[slot];
            } else crow = r;
            float* cp = C + (long long)crow * ldc;
            if (SWIGLU) {
#pragma unroll
                for (int t2 = 0; t2 < 4; t2++) {
                    float g0 = acc[mt][t2 * 2][h * 2 + 0];
                    float g1 = acc[mt][t2 * 2][h * 2 + 1];
                    float u0 = acc[mt][t2 * 2 + 1][h * 2 + 0];
                    float u1 = acc[mt][t2 * 2 + 1][h * 2 + 1];
                    float2 o;
                    o.x = g0 / (1.f + expf(-g0)) * u0;
                    o.y = g1 / (1.f + expf(-g1)) * u1;
                    if (CVTOUT) {
                        o.x = __uint_as_float(f2tf(o.x));
                        o.y = __uint_as_float(f2tf(o.y));
                    }
                    *(float2*)(cp + c0 + (wn * 4 + t2) * 8 + tig * 2) = o;
                }
            } else {
#pragma unroll
                for (int j = 0; j < 8; j++) {
                    float2 o;
                    o.x = acc[mt][j][h * 2 + 0] * scale;
                    o.y = acc[mt][j][h * 2 + 1] * scale;
                    if (CVTOUT) {
                        o.x = __uint_as_float(f2tf(o.x));
                        o.y = __uint_as_float(f2tf(o.y));
                    }
                    *(float2*)(cp + c0 + (wn * 8 + j) * 8 + tig * 2) = o;
                }
            }
        }
    }
}

// ---------------- combine ----------------
__global__ void combine_kernel(float* __restrict__ out) {
    long long i = (long long)blockIdx.x * blockDim.x + threadIdx.x;
    const long long nf4 = (long long)T_TOK * DDIM / 4;
    if (i >= nf4) return;
    long long t = i / (DDIM / 4);
    int c = (int)(i % (DDIM / 4)) * 4;
    float4 o = *(float4*)(out + t * DDIM + c);
#pragma unroll
    for (int s = 0; s < KTOP; s++) {
        const float4 y = *(const float4*)(g_y_moe + ((t * KTOP + s) * (long long)DDIM) + c);
        o.x += y.x; o.y += y.y; o.z += y.z; o.w += y.w;
    }
    *(float4*)(out + t * DDIM + c) = o;
}

// ---------------- host ----------------
static float* sym_f(const void* symbol) {
    void* p = nullptr;
    cudaGetSymbolAddress(&p, symbol);
    return (float*)p;
}

extern "C" void kernel_launch(void* const* d_in, const int* in_sizes, int n_in,
                              void* d_out, int out_size) {
    (void)in_sizes; (void)n_in; (void)out_size;
    const float* x    = (const float*)d_in[0];
    const float* gw   = (const float*)d_in[1];
    const float* gb   = (const float*)d_in[2];
    const float* wgu  = (const float*)d_in[3];
    const float* wd   = (const float*)d_in[4];
    const float* wsgu = (const float*)d_in[5];
    const float* wsd  = (const float*)d_in[6];
    float* out = (float*)d_out;

    float* h_shared = sym_f(g_h_shared);
    float* h_moe    = sym_f(g_h_moe);
    float* y_moe    = sym_f(g_y_moe);
    float* x_t      = sym_f(g_x_t);

    cudaFuncSetAttribute(tgemm<false, true,  false, 0, true >, cudaFuncAttributeMaxDynamicSharedMemorySize, SM_BYTES);
    cudaFuncSetAttribute(tgemm<false, false, false, 0, false>, cudaFuncAttributeMaxDynamicSharedMemorySize, SM_BYTES);
    cudaFuncSetAttribute(tgemm<true,  true,  false, 2, true >, cudaFuncAttributeMaxDynamicSharedMemorySize, SM_BYTES);
    cudaFuncSetAttribute(tgemm<true,  false, true,  0, false>, cudaFuncAttributeMaxDynamicSharedMemorySize, SM_BYTES);

    size_t n_x = (size_t)T_TOK * DDIM / 4;

    // Two-track fork/join (graph-capture-legal: kernel launches + event deps only).
    cudaStream_t s2 = 0;
    cudaEvent_t evFork = 0, evX = 0, evB = 0;
    cudaStreamCreateWithFlags(&s2, cudaStreamNonBlocking);
    cudaEventCreateWithFlags(&evFork, cudaEventDisableTiming);
    cudaEventCreateWithFlags(&evX,    cudaEventDisableTiming);
    cudaEventCreateWithFlags(&evB,    cudaEventDisableTiming);

    cudaEventRecord(evFork, 0);
    cudaStreamWaitEvent(s2, evFork, 0);

    // ---- Track A (default stream): x cvt + shared-expert chain ----
    cvt_kernel<<<(int)(n_x / 2048), 256>>>((const float4*)x, (float4*)x_t, (int)n_x);
    cudaEventRecord(evX, 0);
    // shared gate_up + SwiGLU: x_t @ wsgu(raw) -> h_shared (tf32-rounded)
    tgemm<false, true, false, 0, true>
        <<<dim3(SIDIM / 64, T_TOK / 128, 1), 256, SM_BYTES>>>(
            x_t, wsgu, h_shared, DDIM, DDIM, 2 * SIDIM, SIDIM, 0, SIDIM);
    // shared down: h_shared @ wsd(raw) -> out (dense write covers poison)
    tgemm<false, false, false, 0, false>
        <<<dim3(DDIM / 128, T_TOK / 128, 1), 256, SM_BYTES>>>(
            h_shared, wsd, out, SIDIM, SIDIM, DDIM, DDIM, 0, 0);

    // ---- Track B (s2): router + routed-expert chain ----
    init_kernel<<<1, 32, 0, s2>>>();
    router_kernel<<<T_TOK / 8, 256, 0, s2>>>(x, gw, gb);
    cudaStreamWaitEvent(s2, evX, 0);
    // routed gate_up + SwiGLU (gather tokens): x_t @ wgu[e](raw) -> h_moe (tf32-rounded)
    tgemm<true, true, false, 2, true>
        <<<dim3(IDIM / 64, T_TOK / 128, NEXP), 256, SM_BYTES, s2>>>(
            x_t, wgu, h_moe, DDIM, DDIM, 2 * IDIM, IDIM,
            (long long)DDIM * 2 * IDIM, IDIM);
    // routed down (gather slots, scale): h_moe @ wd[e](raw) -> y_moe
    tgemm<true, false, true, 0, false>
        <<<dim3(DDIM / 128, T_TOK / 128, NEXP), 256, SM_BYTES, s2>>>(
            h_moe, wd, y_moe, IDIM, IDIM, DDIM, DDIM,
            (long long)IDIM * DDIM, 0);
    cudaEventRecord(evB, s2);

    // ---- join on default stream ----
    cudaStreamWaitEvent(0, evB, 0);
    combine_kernel<<<(T_TOK * DDIM / 4 + 255) / 256, 256>>>(out);
    // Handles intentionally not destroyed during capture (host-side only).
}